// round 1
// baseline (speedup 1.0000x reference)
#include <cuda_runtime.h>
#include <cstdint>

// Problem constants
#define NN    16384
#define KK    25
#define RR    3
#define DD    256
#define OUTD  256
#define NTOT  100000
#define BAG   8

// Scratch (allocation-free rule: __device__ globals)
__device__ float g_M[OUTD * 4 * DD];        // fused weights M_cat [256][1024]
__device__ float g_X[(size_t)NN * 4 * DD];  // X_cat [16384][1024]  (64 MB)

__device__ __forceinline__ float to_tf32(float x) {
    uint32_t r;
    asm("cvt.rna.tf32.f32 %0, %1;" : "=r"(r) : "f"(x));
    return __uint_as_float(r);
}

// ---------------------------------------------------------------------------
// K1: fuse weights.  M_c = W_comp[:, c*256:(c+1)*256] @ (W_rel[c] | W_self)
//     M_cat[o][c*256+d] = sum_j W_comp[o][c*256+j] * Wsrc_c[j][d]
// ---------------------------------------------------------------------------
__global__ void __launch_bounds__(256) fuse_weights_kernel(
    const float* __restrict__ W_self,
    const float* __restrict__ W_rel,
    const float* __restrict__ W_comp)
{
    int b = blockIdx.x;
    int c = b >> 8;          // 0..3
    int o = b & 255;         // output row
    int d = threadIdx.x;     // 0..255
    const float* Wsrc = (c < 3) ? (W_rel + (size_t)c * OUTD * DD) : W_self;
    const float* wc   = W_comp + (size_t)o * (4 * DD) + c * DD;
    float acc = 0.f;
#pragma unroll 8
    for (int j = 0; j < DD; ++j)
        acc += wc[j] * Wsrc[j * DD + d];
    g_M[(size_t)o * (4 * DD) + c * DD + d] = acc;
}

// ---------------------------------------------------------------------------
// K2: gather + mean.  X_cat[n][c*256 + d]
//     c<3 : mean over 25 neighbor rows of tables_to[c]
//     c==3: table_self[nodes[n]]
// Block = 256 threads = 4 nodes x 64 float4 lanes; grid = (N/4, 4)
// blockIdx.y (relation) is slowest-varying -> relation-sequential L2 locality.
// ---------------------------------------------------------------------------
__global__ void __launch_bounds__(256) gather_mean_kernel(
    const int*   __restrict__ nodes,
    const int*   __restrict__ neigh_idx,
    const float* __restrict__ table_self,
    const float* __restrict__ tables_to)
{
    const int c   = blockIdx.y;
    const int sub = threadIdx.x >> 6;             // node within block (0..3)
    const int d4  = threadIdx.x & 63;             // float4 lane (covers 256 floats)
    const int n   = blockIdx.x * 4 + sub;

    if (c == 3) {
        int i = __ldg(nodes + n);
        float4 v = reinterpret_cast<const float4*>(table_self + (size_t)i * DD)[d4];
        reinterpret_cast<float4*>(g_X + (size_t)n * (4 * DD) + 3 * DD)[d4] = v;
        return;
    }

    __shared__ int s_idx[4][KK];
    // load 4*25 = 100 indices with first 100 threads
    if (threadIdx.x < 4 * KK) {
        int nn = blockIdx.x * 4 + threadIdx.x / KK;
        int kk = threadIdx.x % KK;
        s_idx[threadIdx.x / KK][kk] =
            neigh_idx[((size_t)c * NN + nn) * KK + kk];
    }
    __syncthreads();

    const float* tbl = tables_to + (size_t)c * NTOT * DD;
    float4 acc = make_float4(0.f, 0.f, 0.f, 0.f);
#pragma unroll
    for (int k = 0; k < KK; ++k) {
        int i = s_idx[sub][k];
        float4 v = reinterpret_cast<const float4*>(tbl + (size_t)i * DD)[d4];
        acc.x += v.x; acc.y += v.y; acc.z += v.z; acc.w += v.w;
    }
    const float s = 1.f / (float)KK;
    float4 r = make_float4(acc.x * s, acc.y * s, acc.z * s, acc.w * s);
    reinterpret_cast<float4*>(g_X + (size_t)n * (4 * DD) + (size_t)c * DD)[d4] = r;
}

// ---------------------------------------------------------------------------
// K3: H = relu(X_cat @ M_cat^T); out = bag-mean(H, 8)
// TF32 mma.sync m16n8k8.  CTA tile 128x64, BK=32, 8 warps (4m x 2n),
// warp tile 32x32 (2 m-frags x 4 n-frags).
// ---------------------------------------------------------------------------
#define BM 128
#define BN 64
#define BK 32
#define LDA 33   // padded smem stride

__global__ void __launch_bounds__(256) gemm_relu_bag_kernel(float* __restrict__ out)
{
    __shared__ float smem[8192];                 // 32 KB: staging U epilogue
    float* As = smem;                            // [128][33]
    float* Bs = smem + BM * LDA;                 // [64][33]

    const int tid  = threadIdx.x;
    const int lane = tid & 31;
    const int wid  = tid >> 5;
    const int wm   = wid & 3;                    // warp m index (0..3)
    const int wn   = wid >> 2;                   // warp n index (0..1)
    const int g    = lane >> 2;                  // group id 0..7
    const int t    = lane & 3;                   // thread-in-group 0..3

    const int cta_m = blockIdx.x * BM;
    const int cta_n = blockIdx.y * BN;

    float acc[2][4][4];
#pragma unroll
    for (int i = 0; i < 2; ++i)
#pragma unroll
        for (int j = 0; j < 4; ++j)
#pragma unroll
            for (int r = 0; r < 4; ++r) acc[i][j][r] = 0.f;

    const float* Abase = g_X + (size_t)cta_m * (4 * DD);
    const float* Bbase = g_M + (size_t)cta_n * (4 * DD);

    for (int kc = 0; kc < (4 * DD) / BK; ++kc) {
        __syncthreads();
        // stage A: 128x32 floats -> 1024 float4, 4 per thread
#pragma unroll
        for (int i = 0; i < 4; ++i) {
            int f4  = tid + i * 256;
            int row = f4 >> 3;
            int kq  = (f4 & 7) * 4;
            float4 v = *reinterpret_cast<const float4*>(
                Abase + (size_t)row * (4 * DD) + kc * BK + kq);
            float* dst = &As[row * LDA + kq];
            dst[0] = to_tf32(v.x); dst[1] = to_tf32(v.y);
            dst[2] = to_tf32(v.z); dst[3] = to_tf32(v.w);
        }
        // stage B: 64x32 floats -> 512 float4, 2 per thread
#pragma unroll
        for (int i = 0; i < 2; ++i) {
            int f4  = tid + i * 256;
            int row = f4 >> 3;
            int kq  = (f4 & 7) * 4;
            float4 v = *reinterpret_cast<const float4*>(
                Bbase + (size_t)row * (4 * DD) + kc * BK + kq);
            float* dst = &Bs[row * LDA + kq];
            dst[0] = to_tf32(v.x); dst[1] = to_tf32(v.y);
            dst[2] = to_tf32(v.z); dst[3] = to_tf32(v.w);
        }
        __syncthreads();

#pragma unroll
        for (int kk = 0; kk < BK / 8; ++kk) {
            uint32_t a[2][4];
            const int k0 = kk * 8 + t;
#pragma unroll
            for (int i = 0; i < 2; ++i) {
                int r0 = wm * 32 + i * 16 + g;
                a[i][0] = __float_as_uint(As[r0 * LDA + k0]);
                a[i][1] = __float_as_uint(As[(r0 + 8) * LDA + k0]);
                a[i][2] = __float_as_uint(As[r0 * LDA + k0 + 4]);
                a[i][3] = __float_as_uint(As[(r0 + 8) * LDA + k0 + 4]);
            }
#pragma unroll
            for (int j = 0; j < 4; ++j) {
                int cn = wn * 32 + j * 8 + g;
                uint32_t b0 = __float_as_uint(Bs[cn * LDA + k0]);
                uint32_t b1 = __float_as_uint(Bs[cn * LDA + k0 + 4]);
#pragma unroll
                for (int i = 0; i < 2; ++i) {
                    asm volatile(
                        "mma.sync.aligned.m16n8k8.row.col.f32.tf32.tf32.f32 "
                        "{%0,%1,%2,%3}, {%4,%5,%6,%7}, {%8,%9}, {%0,%1,%2,%3};"
                        : "+f"(acc[i][j][0]), "+f"(acc[i][j][1]),
                          "+f"(acc[i][j][2]), "+f"(acc[i][j][3])
                        : "r"(a[i][0]), "r"(a[i][1]), "r"(a[i][2]), "r"(a[i][3]),
                          "r"(b0), "r"(b1));
                }
            }
        }
    }

    // epilogue: relu -> smem [128][64] -> bag-mean(8) -> out
    __syncthreads();
    float* Cs = smem;
#pragma unroll
    for (int i = 0; i < 2; ++i) {
#pragma unroll
        for (int j = 0; j < 4; ++j) {
            int r0 = wm * 32 + i * 16 + g;
            int c0 = wn * 32 + j * 8 + 2 * t;
            Cs[r0 * BN + c0]           = fmaxf(acc[i][j][0], 0.f);
            Cs[r0 * BN + c0 + 1]       = fmaxf(acc[i][j][1], 0.f);
            Cs[(r0 + 8) * BN + c0]     = fmaxf(acc[i][j][2], 0.f);
            Cs[(r0 + 8) * BN + c0 + 1] = fmaxf(acc[i][j][3], 0.f);
        }
    }
    __syncthreads();

    const int col = tid & 63;
    const int g0  = tid >> 6;                    // 0..3
#pragma unroll
    for (int gg = g0; gg < BM / BAG; gg += 4) {
        float s = 0.f;
#pragma unroll
        for (int r = 0; r < BAG; ++r) s += Cs[(gg * BAG + r) * BN + col];
        out[(size_t)(blockIdx.x * (BM / BAG) + gg) * OUTD + cta_n + col] = s * (1.f / BAG);
    }
}

// ---------------------------------------------------------------------------
extern "C" void kernel_launch(void* const* d_in, const int* in_sizes, int n_in,
                              void* d_out, int out_size)
{
    (void)in_sizes; (void)n_in; (void)out_size;
    const int*   nodes      = (const int*)  d_in[0];
    const int*   neigh_idx  = (const int*)  d_in[1];
    const float* table_self = (const float*)d_in[2];
    const float* tables_to  = (const float*)d_in[3];
    const float* W_self     = (const float*)d_in[4];
    const float* W_rel      = (const float*)d_in[5];
    const float* W_comp     = (const float*)d_in[6];
    float*       out        = (float*)d_out;

    fuse_weights_kernel<<<4 * OUTD, 256>>>(W_self, W_rel, W_comp);
    gather_mean_kernel<<<dim3(NN / 4, 4), 256>>>(nodes, neigh_idx, table_self, tables_to);
    gemm_relu_bag_kernel<<<dim3(NN / BM, OUTD / BN), 256>>>(out);
}

// round 2
// speedup vs baseline: 1.8606x; 1.8606x over previous
#include <cuda_runtime.h>
#include <cstdint>

// Problem constants
#define NN    16384
#define KK    25
#define DD    256
#define OUTD  256
#define NTOT  100000
#define BAG   8
#define KDIM  (4 * DD)   // 1024

// Scratch (allocation-free rule: __device__ globals)
__device__ float g_M[OUTD * KDIM];          // fused weights, TF32-rounded
__device__ float g_X[(size_t)NN * KDIM];    // gathered features, TF32-rounded (64 MB)

__device__ __forceinline__ float to_tf32(float x) {
    uint32_t r;
    asm("cvt.rna.tf32.f32 %0, %1;" : "=r"(r) : "f"(x));
    return __uint_as_float(r);
}

__device__ __forceinline__ void cp_async16(void* smem, const void* gmem) {
    uint32_t s = (uint32_t)__cvta_generic_to_shared(smem);
    asm volatile("cp.async.cg.shared.global [%0], [%1], 16;" :: "r"(s), "l"(gmem));
}

// ---------------------------------------------------------------------------
// K1: fuse weights.  M_c = W_comp[:, c*256:(c+1)*256] @ (W_rel[c] | W_self)
// 16 output rows per block share one streaming pass over Wsrc (16x traffic cut)
// grid = 4 relations x 16 row-tiles = 64 blocks
// ---------------------------------------------------------------------------
__global__ void __launch_bounds__(256) fuse_weights_kernel(
    const float* __restrict__ W_self,
    const float* __restrict__ W_rel,
    const float* __restrict__ W_comp)
{
    const int c  = blockIdx.x >> 4;            // 0..3
    const int o0 = (blockIdx.x & 15) << 4;     // 16-row tile

    __shared__ float s_wc[16 * DD];            // W_comp[o0:o0+16][c*256:+256]
    for (int i = threadIdx.x; i < 16 * DD; i += 256)
        s_wc[i] = W_comp[(size_t)(o0 + (i >> 8)) * KDIM + c * DD + (i & 255)];
    __syncthreads();

    const float* Wsrc = (c < 3) ? (W_rel + (size_t)c * OUTD * DD) : W_self;
    const int d = threadIdx.x;

    float acc[16];
#pragma unroll
    for (int o = 0; o < 16; ++o) acc[o] = 0.f;

#pragma unroll 4
    for (int j = 0; j < DD; ++j) {
        float v = __ldg(Wsrc + (size_t)j * DD + d);
#pragma unroll
        for (int o = 0; o < 16; ++o) acc[o] += s_wc[o * DD + j] * v;
    }
#pragma unroll
    for (int o = 0; o < 16; ++o)
        g_M[(size_t)(o0 + o) * KDIM + c * DD + d] = to_tf32(acc[o]);
}

// ---------------------------------------------------------------------------
// K2: gather + mean -> g_X (TF32-rounded so the GEMM needs no conversion)
// Block = 256 threads = 4 nodes x 64 float4 lanes; grid = (N/4, 4)
// blockIdx.y (relation) slowest-varying -> relation-sequential L2 locality.
// ---------------------------------------------------------------------------
__global__ void __launch_bounds__(256) gather_mean_kernel(
    const int*   __restrict__ nodes,
    const int*   __restrict__ neigh_idx,
    const float* __restrict__ table_self,
    const float* __restrict__ tables_to)
{
    const int c   = blockIdx.y;
    const int sub = threadIdx.x >> 6;
    const int d4  = threadIdx.x & 63;
    const int n   = blockIdx.x * 4 + sub;

    if (c == 3) {
        int i = __ldg(nodes + n);
        float4 v = reinterpret_cast<const float4*>(table_self + (size_t)i * DD)[d4];
        float4 r = make_float4(to_tf32(v.x), to_tf32(v.y), to_tf32(v.z), to_tf32(v.w));
        reinterpret_cast<float4*>(g_X + (size_t)n * KDIM + 3 * DD)[d4] = r;
        return;
    }

    __shared__ int s_idx[4][KK];
    if (threadIdx.x < 4 * KK) {
        int nn = blockIdx.x * 4 + threadIdx.x / KK;
        int kk = threadIdx.x % KK;
        s_idx[threadIdx.x / KK][kk] = neigh_idx[((size_t)c * NN + nn) * KK + kk];
    }
    __syncthreads();

    const float* tbl = tables_to + (size_t)c * NTOT * DD;
    float4 acc = make_float4(0.f, 0.f, 0.f, 0.f);
#pragma unroll
    for (int k = 0; k < KK; ++k) {
        int i = s_idx[sub][k];
        float4 v = reinterpret_cast<const float4*>(tbl + (size_t)i * DD)[d4];
        acc.x += v.x; acc.y += v.y; acc.z += v.z; acc.w += v.w;
    }
    const float s = 1.f / (float)KK;
    float4 r = make_float4(to_tf32(acc.x * s), to_tf32(acc.y * s),
                           to_tf32(acc.z * s), to_tf32(acc.w * s));
    reinterpret_cast<float4*>(g_X + (size_t)n * KDIM + (size_t)c * DD)[d4] = r;
}

// ---------------------------------------------------------------------------
// K3: H = relu(X @ M^T); out = bag-mean(H, 8)
// TF32 mma.sync m16n8k8. CTA 128x128, BK=32, cp.async double-buffered.
// 8 warps (4m x 2n), warp tile 32x64 (2 m-frags x 8 n-frags).
// ---------------------------------------------------------------------------
#define BM 128
#define BN 128
#define BK 32
#define LDS 36               // 32 + 4 pad (keeps 16B alignment)
#define STAGE_F (BM * LDS)   // floats per matrix per stage (4608)
#define NKC (KDIM / BK)      // 32 k-panels
#define GEMM_SMEM_BYTES (4 * STAGE_F * 4)   // 73728 B

__global__ void __launch_bounds__(256, 2) gemm_relu_bag_kernel(float* __restrict__ out)
{
    extern __shared__ float smem[];
    float* sA[2] = { smem,              smem + STAGE_F };
    float* sB[2] = { smem + 2 * STAGE_F, smem + 3 * STAGE_F };

    const int tid  = threadIdx.x;
    const int lane = tid & 31;
    const int wid  = tid >> 5;
    const int wm   = wid & 3;            // 0..3 -> rows wm*32
    const int wn   = wid >> 2;           // 0..1 -> cols wn*64
    const int g    = lane >> 2;          // 0..7
    const int t    = lane & 3;           // 0..3

    const float* Abase = g_X + (size_t)blockIdx.x * BM * KDIM;
    const float* Bbase = g_M + (size_t)blockIdx.y * BN * KDIM;

    // staging coords (4 float4 for A, 4 for B per thread per stage)
    const int srow = tid >> 3;           // 0..31 step base
    const int scol = (tid & 7) * 4;      // float offset within 32-wide panel

    float acc[2][8][4];
#pragma unroll
    for (int i = 0; i < 2; ++i)
#pragma unroll
        for (int j = 0; j < 8; ++j)
#pragma unroll
            for (int r = 0; r < 4; ++r) acc[i][j][r] = 0.f;

    // ---- stage 0 ----
#pragma unroll
    for (int i = 0; i < 4; ++i) {
        int row = srow + i * 32;
        cp_async16(&sA[0][row * LDS + scol], Abase + (size_t)row * KDIM + scol);
        cp_async16(&sB[0][row * LDS + scol], Bbase + (size_t)row * KDIM + scol);
    }
    asm volatile("cp.async.commit_group;");

    for (int kc = 0; kc < NKC; ++kc) {
        const int cur = kc & 1;
        if (kc + 1 < NKC) {
            const int nb = 1 - cur;
            const int ko = (kc + 1) * BK;
#pragma unroll
            for (int i = 0; i < 4; ++i) {
                int row = srow + i * 32;
                cp_async16(&sA[nb][row * LDS + scol], Abase + (size_t)row * KDIM + ko + scol);
                cp_async16(&sB[nb][row * LDS + scol], Bbase + (size_t)row * KDIM + ko + scol);
            }
            asm volatile("cp.async.commit_group;");
            asm volatile("cp.async.wait_group 1;");
        } else {
            asm volatile("cp.async.wait_group 0;");
        }
        __syncthreads();

        const float* As = sA[cur];
        const float* Bs = sB[cur];
#pragma unroll
        for (int kk = 0; kk < BK / 8; ++kk) {
            const int k0 = kk * 8 + t;
            uint32_t a[2][4];
#pragma unroll
            for (int mi = 0; mi < 2; ++mi) {
                int r0 = wm * 32 + mi * 16 + g;
                a[mi][0] = __float_as_uint(As[r0 * LDS + k0]);
                a[mi][1] = __float_as_uint(As[(r0 + 8) * LDS + k0]);
                a[mi][2] = __float_as_uint(As[r0 * LDS + k0 + 4]);
                a[mi][3] = __float_as_uint(As[(r0 + 8) * LDS + k0 + 4]);
            }
#pragma unroll
            for (int nj = 0; nj < 8; ++nj) {
                int cn = wn * 64 + nj * 8 + g;
                uint32_t b0 = __float_as_uint(Bs[cn * LDS + k0]);
                uint32_t b1 = __float_as_uint(Bs[cn * LDS + k0 + 4]);
#pragma unroll
                for (int mi = 0; mi < 2; ++mi) {
                    asm volatile(
                        "mma.sync.aligned.m16n8k8.row.col.f32.tf32.tf32.f32 "
                        "{%0,%1,%2,%3}, {%4,%5,%6,%7}, {%8,%9}, {%0,%1,%2,%3};"
                        : "+f"(acc[mi][nj][0]), "+f"(acc[mi][nj][1]),
                          "+f"(acc[mi][nj][2]), "+f"(acc[mi][nj][3])
                        : "r"(a[mi][0]), "r"(a[mi][1]), "r"(a[mi][2]), "r"(a[mi][3]),
                          "r"(b0), "r"(b1));
                }
            }
        }
        __syncthreads();
    }

    // ---- epilogue: relu -> smem [128][128] -> bag-mean(8) -> out ----
    float* Cs = smem;
#pragma unroll
    for (int mi = 0; mi < 2; ++mi) {
#pragma unroll
        for (int nj = 0; nj < 8; ++nj) {
            int r0 = wm * 32 + mi * 16 + g;
            int c0 = wn * 64 + nj * 8 + 2 * t;
            Cs[r0 * BN + c0]           = fmaxf(acc[mi][nj][0], 0.f);
            Cs[r0 * BN + c0 + 1]       = fmaxf(acc[mi][nj][1], 0.f);
            Cs[(r0 + 8) * BN + c0]     = fmaxf(acc[mi][nj][2], 0.f);
            Cs[(r0 + 8) * BN + c0 + 1] = fmaxf(acc[mi][nj][3], 0.f);
        }
    }
    __syncthreads();

    const int col = tid & 127;
    const int h   = tid >> 7;            // 0..1
#pragma unroll
    for (int gg = h; gg < BM / BAG; gg += 2) {
        float s = 0.f;
#pragma unroll
        for (int r = 0; r < BAG; ++r) s += Cs[(gg * BAG + r) * BN + col];
        out[(size_t)(blockIdx.x * (BM / BAG) + gg) * OUTD + blockIdx.y * BN + col]
            = s * (1.f / BAG);
    }
}

// ---------------------------------------------------------------------------
extern "C" void kernel_launch(void* const* d_in, const int* in_sizes, int n_in,
                              void* d_out, int out_size)
{
    (void)in_sizes; (void)n_in; (void)out_size;
    const int*   nodes      = (const int*)  d_in[0];
    const int*   neigh_idx  = (const int*)  d_in[1];
    const float* table_self = (const float*)d_in[2];
    const float* tables_to  = (const float*)d_in[3];
    const float* W_self     = (const float*)d_in[4];
    const float* W_rel      = (const float*)d_in[5];
    const float* W_comp     = (const float*)d_in[6];
    float*       out        = (float*)d_out;

    cudaFuncSetAttribute(gemm_relu_bag_kernel,
                         cudaFuncAttributeMaxDynamicSharedMemorySize,
                         GEMM_SMEM_BYTES);

    fuse_weights_kernel<<<64, 256>>>(W_self, W_rel, W_comp);
    gather_mean_kernel<<<dim3(NN / 4, 4), 256>>>(nodes, neigh_idx, table_self, tables_to);
    gemm_relu_bag_kernel<<<dim3(NN / BM, OUTD / BN), 256, GEMM_SMEM_BYTES>>>(out);
}

// round 3
// speedup vs baseline: 2.1132x; 1.1357x over previous
#include <cuda_runtime.h>
#include <cstdint>

// Problem constants
#define NN    16384
#define KK    25
#define DD    256
#define OUTD  256
#define NTOT  100000
#define BAG   8
#define KDIM  (4 * DD)   // 1024

// Scratch (allocation-free rule: __device__ globals)
__device__ float g_M[OUTD * KDIM];          // fused weights, TF32-rounded
__device__ float g_X[(size_t)NN * KDIM];    // gathered features, TF32-rounded (64 MB)

__device__ __forceinline__ float to_tf32(float x) {
    uint32_t r;
    asm("cvt.rna.tf32.f32 %0, %1;" : "=r"(r) : "f"(x));
    return __uint_as_float(r);
}

__device__ __forceinline__ void cp_async16(void* smem, const void* gmem) {
    uint32_t s = (uint32_t)__cvta_generic_to_shared(smem);
    asm volatile("cp.async.cg.shared.global [%0], [%1], 16;" :: "r"(s), "l"(gmem));
}

// ---------------------------------------------------------------------------
// K1: fuse weights.  M_c = W_comp[:, c*256:(c+1)*256] @ (W_rel[c] | W_self)
// 8 o-rows per block, W_comp slice transposed in smem ([j][o]) so the inner
// loop is 2x LDS.128 broadcast + 8 FFMA.  grid = 4 relations x 32 = 128 blocks.
// ---------------------------------------------------------------------------
#define FO 8
__global__ void __launch_bounds__(256) fuse_weights_kernel(
    const float* __restrict__ W_self,
    const float* __restrict__ W_rel,
    const float* __restrict__ W_comp)
{
    const int c  = blockIdx.x >> 5;            // 0..3
    const int o0 = (blockIdx.x & 31) * FO;     // 8-row tile

    __shared__ float s_w[DD * FO];             // transposed: s_w[j*FO + o]
    for (int i = threadIdx.x; i < DD * FO; i += 256) {
        int o = i & (FO - 1);
        int j = i >> 3;
        s_w[i] = W_comp[(size_t)(o0 + o) * KDIM + c * DD + j];
    }
    __syncthreads();

    const float* Wsrc = (c < 3) ? (W_rel + (size_t)c * OUTD * DD) : W_self;
    const int d = threadIdx.x;

    float acc[FO];
#pragma unroll
    for (int o = 0; o < FO; ++o) acc[o] = 0.f;

#pragma unroll 4
    for (int j = 0; j < DD; ++j) {
        float v = __ldg(Wsrc + (size_t)j * DD + d);
        float4 w0 = *reinterpret_cast<const float4*>(&s_w[j * FO]);
        float4 w1 = *reinterpret_cast<const float4*>(&s_w[j * FO + 4]);
        acc[0] += w0.x * v; acc[1] += w0.y * v;
        acc[2] += w0.z * v; acc[3] += w0.w * v;
        acc[4] += w1.x * v; acc[5] += w1.y * v;
        acc[6] += w1.z * v; acc[7] += w1.w * v;
    }
#pragma unroll
    for (int o = 0; o < FO; ++o)
        g_M[(size_t)(o0 + o) * KDIM + c * DD + d] = to_tf32(acc[o]);
}

// ---------------------------------------------------------------------------
// K2: gather + mean -> g_X (TF32-rounded so the GEMM needs no conversion)
// Block = 256 threads = 4 nodes x 64 float4 lanes; grid = (N/4, 4)
// blockIdx.y (relation) slowest-varying -> relation-sequential L2 locality.
// ---------------------------------------------------------------------------
__global__ void __launch_bounds__(256) gather_mean_kernel(
    const int*   __restrict__ nodes,
    const int*   __restrict__ neigh_idx,
    const float* __restrict__ table_self,
    const float* __restrict__ tables_to)
{
    const int c   = blockIdx.y;
    const int sub = threadIdx.x >> 6;
    const int d4  = threadIdx.x & 63;
    const int n   = blockIdx.x * 4 + sub;

    if (c == 3) {
        int i = __ldg(nodes + n);
        float4 v = reinterpret_cast<const float4*>(table_self + (size_t)i * DD)[d4];
        float4 r = make_float4(to_tf32(v.x), to_tf32(v.y), to_tf32(v.z), to_tf32(v.w));
        reinterpret_cast<float4*>(g_X + (size_t)n * KDIM + 3 * DD)[d4] = r;
        return;
    }

    __shared__ int s_idx[4][KK];
    if (threadIdx.x < 4 * KK) {
        int nn = blockIdx.x * 4 + threadIdx.x / KK;
        int kk = threadIdx.x % KK;
        s_idx[threadIdx.x / KK][kk] = neigh_idx[((size_t)c * NN + nn) * KK + kk];
    }
    __syncthreads();

    const float* tbl = tables_to + (size_t)c * NTOT * DD;
    float4 acc = make_float4(0.f, 0.f, 0.f, 0.f);
#pragma unroll
    for (int k = 0; k < KK; ++k) {
        int i = s_idx[sub][k];
        float4 v = reinterpret_cast<const float4*>(tbl + (size_t)i * DD)[d4];
        acc.x += v.x; acc.y += v.y; acc.z += v.z; acc.w += v.w;
    }
    const float s = 1.f / (float)KK;
    float4 r = make_float4(to_tf32(acc.x * s), to_tf32(acc.y * s),
                           to_tf32(acc.z * s), to_tf32(acc.w * s));
    reinterpret_cast<float4*>(g_X + (size_t)n * KDIM + (size_t)c * DD)[d4] = r;
}

// ---------------------------------------------------------------------------
// K3: H = relu(X @ M^T); out = bag-mean(H, 8)
// TF32 mma.sync m16n8k8. CTA 128x128, BK=32, cp.async double-buffered.
// 8 warps (4m x 2n), warp tile 32x64 (2 m-frags x 8 n-frags).
// ---------------------------------------------------------------------------
#define BM 128
#define BN 128
#define BK 32
#define LDS 36               // 32 + 4 pad (keeps 16B alignment)
#define STAGE_F (BM * LDS)   // floats per matrix per stage (4608)
#define NKC (KDIM / BK)      // 32 k-panels
#define GEMM_SMEM_BYTES (4 * STAGE_F * 4)   // 73728 B

__global__ void __launch_bounds__(256, 2) gemm_relu_bag_kernel(float* __restrict__ out)
{
    extern __shared__ float smem[];
    float* sA[2] = { smem,              smem + STAGE_F };
    float* sB[2] = { smem + 2 * STAGE_F, smem + 3 * STAGE_F };

    const int tid  = threadIdx.x;
    const int lane = tid & 31;
    const int wid  = tid >> 5;
    const int wm   = wid & 3;            // 0..3 -> rows wm*32
    const int wn   = wid >> 2;           // 0..1 -> cols wn*64
    const int g    = lane >> 2;          // 0..7
    const int t    = lane & 3;           // 0..3

    const float* Abase = g_X + (size_t)blockIdx.x * BM * KDIM;
    const float* Bbase = g_M + (size_t)blockIdx.y * BN * KDIM;

    const int srow = tid >> 3;           // 0..31 step base
    const int scol = (tid & 7) * 4;      // float offset within 32-wide panel

    float acc[2][8][4];
#pragma unroll
    for (int i = 0; i < 2; ++i)
#pragma unroll
        for (int j = 0; j < 8; ++j)
#pragma unroll
            for (int r = 0; r < 4; ++r) acc[i][j][r] = 0.f;

    // ---- stage 0 ----
#pragma unroll
    for (int i = 0; i < 4; ++i) {
        int row = srow + i * 32;
        cp_async16(&sA[0][row * LDS + scol], Abase + (size_t)row * KDIM + scol);
        cp_async16(&sB[0][row * LDS + scol], Bbase + (size_t)row * KDIM + scol);
    }
    asm volatile("cp.async.commit_group;");

    for (int kc = 0; kc < NKC; ++kc) {
        const int cur = kc & 1;
        if (kc + 1 < NKC) {
            const int nb = 1 - cur;
            const int ko = (kc + 1) * BK;
#pragma unroll
            for (int i = 0; i < 4; ++i) {
                int row = srow + i * 32;
                cp_async16(&sA[nb][row * LDS + scol], Abase + (size_t)row * KDIM + ko + scol);
                cp_async16(&sB[nb][row * LDS + scol], Bbase + (size_t)row * KDIM + ko + scol);
            }
            asm volatile("cp.async.commit_group;");
            asm volatile("cp.async.wait_group 1;");
        } else {
            asm volatile("cp.async.wait_group 0;");
        }
        __syncthreads();

        const float* As = sA[cur];
        const float* Bs = sB[cur];
#pragma unroll
        for (int kk = 0; kk < BK / 8; ++kk) {
            const int k0 = kk * 8 + t;
            uint32_t a[2][4];
#pragma unroll
            for (int mi = 0; mi < 2; ++mi) {
                int r0 = wm * 32 + mi * 16 + g;
                a[mi][0] = __float_as_uint(As[r0 * LDS + k0]);
                a[mi][1] = __float_as_uint(As[(r0 + 8) * LDS + k0]);
                a[mi][2] = __float_as_uint(As[r0 * LDS + k0 + 4]);
                a[mi][3] = __float_as_uint(As[(r0 + 8) * LDS + k0 + 4]);
            }
#pragma unroll
            for (int nj = 0; nj < 8; ++nj) {
                int cn = wn * 64 + nj * 8 + g;
                uint32_t b0 = __float_as_uint(Bs[cn * LDS + k0]);
                uint32_t b1 = __float_as_uint(Bs[cn * LDS + k0 + 4]);
#pragma unroll
                for (int mi = 0; mi < 2; ++mi) {
                    asm volatile(
                        "mma.sync.aligned.m16n8k8.row.col.f32.tf32.tf32.f32 "
                        "{%0,%1,%2,%3}, {%4,%5,%6,%7}, {%8,%9}, {%0,%1,%2,%3};"
                        : "+f"(acc[mi][nj][0]), "+f"(acc[mi][nj][1]),
                          "+f"(acc[mi][nj][2]), "+f"(acc[mi][nj][3])
                        : "r"(a[mi][0]), "r"(a[mi][1]), "r"(a[mi][2]), "r"(a[mi][3]),
                          "r"(b0), "r"(b1));
                }
            }
        }
        __syncthreads();
    }

    // ---- epilogue: relu -> smem [128][128] -> bag-mean(8) -> out ----
    float* Cs = smem;
#pragma unroll
    for (int mi = 0; mi < 2; ++mi) {
#pragma unroll
        for (int nj = 0; nj < 8; ++nj) {
            int r0 = wm * 32 + mi * 16 + g;
            int c0 = wn * 64 + nj * 8 + 2 * t;
            Cs[r0 * BN + c0]           = fmaxf(acc[mi][nj][0], 0.f);
            Cs[r0 * BN + c0 + 1]       = fmaxf(acc[mi][nj][1], 0.f);
            Cs[(r0 + 8) * BN + c0]     = fmaxf(acc[mi][nj][2], 0.f);
            Cs[(r0 + 8) * BN + c0 + 1] = fmaxf(acc[mi][nj][3], 0.f);
        }
    }
    __syncthreads();

    const int col = tid & 127;
    const int h   = tid >> 7;            // 0..1
#pragma unroll
    for (int gg = h; gg < BM / BAG; gg += 2) {
        float s = 0.f;
#pragma unroll
        for (int r = 0; r < BAG; ++r) s += Cs[(gg * BAG + r) * BN + col];
        out[(size_t)(blockIdx.x * (BM / BAG) + gg) * OUTD + blockIdx.y * BN + col]
            = s * (1.f / BAG);
    }
}

// ---------------------------------------------------------------------------
extern "C" void kernel_launch(void* const* d_in, const int* in_sizes, int n_in,
                              void* d_out, int out_size)
{
    (void)in_sizes; (void)n_in; (void)out_size;
    const int*   nodes      = (const int*)  d_in[0];
    const int*   neigh_idx  = (const int*)  d_in[1];
    const float* table_self = (const float*)d_in[2];
    const float* tables_to  = (const float*)d_in[3];
    const float* W_self     = (const float*)d_in[4];
    const float* W_rel      = (const float*)d_in[5];
    const float* W_comp     = (const float*)d_in[6];
    float*       out        = (float*)d_out;

    cudaFuncSetAttribute(gemm_relu_bag_kernel,
                         cudaFuncAttributeMaxDynamicSharedMemorySize,
                         GEMM_SMEM_BYTES);

    // gather first (independent of fuse) so the fixed ncu sample slot lands
    // on the gather kernel next profile.
    gather_mean_kernel<<<dim3(NN / 4, 4), 256>>>(nodes, neigh_idx, table_self, tables_to);
    fuse_weights_kernel<<<128, 256>>>(W_self, W_rel, W_comp);
    gemm_relu_bag_kernel<<<dim3(NN / BM, OUTD / BN), 256, GEMM_SMEM_BYTES>>>(out);
}

// round 4
// speedup vs baseline: 2.4069x; 1.1390x over previous
#include <cuda_runtime.h>
#include <cstdint>

// Problem constants
#define NN    16384
#define KK    25
#define DD    256
#define OUTD  256
#define NTOT  100000
#define BAG   8
#define KDIM  (4 * DD)   // 1024

// K-dimension layout of g_X / g_M is pair-permuted within each 8-float block:
//   [k0,k4,k1,k5,k2,k6,k3,k7]
// so a tf32 mma fragment pair (k, k+4) is contiguous (one LDS.64).
// Both operands use it, so the GEMM result is unchanged.

__device__ float g_M[OUTD * KDIM];          // fused weights, TF32, permuted K
__device__ float g_X[(size_t)NN * KDIM];    // features, TF32, permuted K (64 MB)

__device__ __forceinline__ float to_tf32(float x) {
    uint32_t r;
    asm("cvt.rna.tf32.f32 %0, %1;" : "=r"(r) : "f"(x));
    return __uint_as_float(r);
}

__device__ __forceinline__ void cp_async16(void* smem, const void* gmem) {
    uint32_t s = (uint32_t)__cvta_generic_to_shared(smem);
    asm volatile("cp.async.cg.shared.global [%0], [%1], 16;" :: "r"(s), "l"(gmem));
}

// ---------------------------------------------------------------------------
// K1: fuse weights.  M_c = W_comp[:, c*256:(c+1)*256] @ (W_rel[c] | W_self)
// FO=2 o-rows per block -> 512 blocks (full chip).  Inner loop:
// 1 LDG + 1 LDS.64 + 2 FFMA, unroll 8 for MLP.
// ---------------------------------------------------------------------------
__global__ void __launch_bounds__(256) fuse_weights_kernel(
    const float* __restrict__ W_self,
    const float* __restrict__ W_rel,
    const float* __restrict__ W_comp)
{
    const int c  = blockIdx.x >> 7;            // 0..3
    const int o0 = (blockIdx.x & 127) * 2;     // 2-row tile

    __shared__ float2 s_w[DD];                 // (W_comp[o0][j], W_comp[o0+1][j])
    {
        int j = threadIdx.x;
        s_w[j] = make_float2(W_comp[(size_t)o0 * KDIM + c * DD + j],
                             W_comp[(size_t)(o0 + 1) * KDIM + c * DD + j]);
    }
    __syncthreads();

    const float* Wsrc = (c < 3) ? (W_rel + (size_t)c * OUTD * DD) : W_self;
    const int d = threadIdx.x;

    float acc0 = 0.f, acc1 = 0.f;
#pragma unroll 8
    for (int j = 0; j < DD; ++j) {
        float v = __ldg(Wsrc + (size_t)j * DD + d);
        float2 w = s_w[j];
        acc0 += w.x * v;
        acc1 += w.y * v;
    }
    const int pd = (d & ~7) | ((d & 3) << 1) | ((d >> 2) & 1);   // pair-permute
    g_M[(size_t)o0 * KDIM + c * DD + pd]       = to_tf32(acc0);
    g_M[(size_t)(o0 + 1) * KDIM + c * DD + pd] = to_tf32(acc1);
}

// ---------------------------------------------------------------------------
// K2: gather + mean -> g_X (TF32, pair-permuted K layout)
// Block = 256 threads = 4 nodes x 64 float4 lanes; grid = (N/4, 4)
// ---------------------------------------------------------------------------
__global__ void __launch_bounds__(256) gather_mean_kernel(
    const int*   __restrict__ nodes,
    const int*   __restrict__ neigh_idx,
    const float* __restrict__ table_self,
    const float* __restrict__ tables_to)
{
    const int c   = blockIdx.y;
    const int sub = threadIdx.x >> 6;
    const int d4  = threadIdx.x & 63;
    const int n   = blockIdx.x * 4 + sub;

    if (c == 3) {
        int i = __ldg(nodes + n);
        float4 v = reinterpret_cast<const float4*>(table_self + (size_t)i * DD)[d4];
        float* dst = g_X + (size_t)n * KDIM + 3 * DD + ((d4 >> 1) << 3) + (d4 & 1);
        dst[0] = to_tf32(v.x); dst[2] = to_tf32(v.y);
        dst[4] = to_tf32(v.z); dst[6] = to_tf32(v.w);
        return;
    }

    __shared__ int s_idx[4][KK];
    if (threadIdx.x < 4 * KK) {
        int nn = blockIdx.x * 4 + threadIdx.x / KK;
        int kk = threadIdx.x % KK;
        s_idx[threadIdx.x / KK][kk] = neigh_idx[((size_t)c * NN + nn) * KK + kk];
    }
    __syncthreads();

    const float* tbl = tables_to + (size_t)c * NTOT * DD;
    float4 acc = make_float4(0.f, 0.f, 0.f, 0.f);
#pragma unroll
    for (int k = 0; k < KK; ++k) {
        int i = s_idx[sub][k];
        float4 v = reinterpret_cast<const float4*>(tbl + (size_t)i * DD)[d4];
        acc.x += v.x; acc.y += v.y; acc.z += v.z; acc.w += v.w;
    }
    const float s = 1.f / (float)KK;
    float* dst = g_X + (size_t)n * KDIM + (size_t)c * DD + ((d4 >> 1) << 3) + (d4 & 1);
    dst[0] = to_tf32(acc.x * s); dst[2] = to_tf32(acc.y * s);
    dst[4] = to_tf32(acc.z * s); dst[6] = to_tf32(acc.w * s);
}

// ---------------------------------------------------------------------------
// K3: H = relu(X @ M^T); out = bag-mean(H, 8)
// TF32 mma m16n8k8. CTA 128x128, BK=32, 3-stage cp.async, XOR-swizzled smem,
// LDS.64 fragment loads via the pair-permuted gmem layout.
// 8 warps (4m x 2n), warp tile 32x64.
// ---------------------------------------------------------------------------
#define BM 128
#define BN 128
#define BK 32
#define NKC (KDIM / BK)                 // 32
#define STAGE_F (BM * BK + BN * BK)     // 8192 floats per stage
#define GEMM_SMEM_BYTES (3 * STAGE_F * 4)   // 98304 B

__global__ void __launch_bounds__(256, 2) gemm_relu_bag_kernel(float* __restrict__ out)
{
    extern __shared__ float smem[];

    const int tid  = threadIdx.x;
    const int lane = tid & 31;
    const int wid  = tid >> 5;
    const int wm   = wid & 3;            // rows wm*32
    const int wn   = wid >> 2;           // cols wn*64
    const int g    = lane >> 2;          // 0..7
    const int t    = lane & 3;           // 0..3

    const float* Abase = g_X + (size_t)blockIdx.x * BM * KDIM;
    const float* Bbase = g_M + (size_t)blockIdx.y * BN * KDIM;

    float acc[2][8][4];
#pragma unroll
    for (int i = 0; i < 2; ++i)
#pragma unroll
        for (int j = 0; j < 8; ++j)
#pragma unroll
            for (int r = 0; r < 4; ++r) acc[i][j][r] = 0.f;

    // staging: 1024 16B chunks per matrix per stage; 4 each per thread
#define STAGE_FILL(slot, ko)                                                   \
    {                                                                          \
        float* sA_ = smem + (slot) * STAGE_F;                                  \
        float* sB_ = sA_ + BM * BK;                                            \
        _Pragma("unroll")                                                      \
        for (int i_ = 0; i_ < 4; ++i_) {                                       \
            int f4_ = tid + i_ * 256;                                          \
            int r_  = f4_ >> 3;                                                \
            int c_  = f4_ & 7;                                                 \
            int cs_ = c_ ^ (r_ & 7);                                           \
            cp_async16(sA_ + r_ * BK + cs_ * 4,                                \
                       Abase + (size_t)r_ * KDIM + (ko) + c_ * 4);             \
            cp_async16(sB_ + r_ * BK + cs_ * 4,                                \
                       Bbase + (size_t)r_ * KDIM + (ko) + c_ * 4);             \
        }                                                                      \
        asm volatile("cp.async.commit_group;");                                \
    }

    STAGE_FILL(0, 0)
    STAGE_FILL(1, BK)

    for (int kc = 0; kc < NKC; ++kc) {
        if (kc + 1 < NKC) asm volatile("cp.async.wait_group 1;");
        else              asm volatile("cp.async.wait_group 0;");
        __syncthreads();

        if (kc + 2 < NKC) STAGE_FILL((kc + 2) % 3, (kc + 2) * BK)

        const float* As = smem + (kc % 3) * STAGE_F;
        const float* Bs = As + BM * BK;

#pragma unroll
        for (int kk = 0; kk < BK / 8; ++kk) {
            // swizzled word offset within a row for this (kk, t, g)
            const int cidx = (((kk * 2 + (t >> 1)) ^ g) << 2) + ((t & 1) << 1);

            float2 a0[2], a1[2];
#pragma unroll
            for (int mi = 0; mi < 2; ++mi) {
                int r0 = wm * 32 + mi * 16 + g;
                a0[mi] = *reinterpret_cast<const float2*>(As + r0 * BK + cidx);
                a1[mi] = *reinterpret_cast<const float2*>(As + (r0 + 8) * BK + cidx);
            }
#pragma unroll
            for (int nj = 0; nj < 8; ++nj) {
                int cn = wn * 64 + nj * 8 + g;
                float2 b = *reinterpret_cast<const float2*>(Bs + cn * BK + cidx);
                uint32_t ub0 = __float_as_uint(b.x);
                uint32_t ub1 = __float_as_uint(b.y);
#pragma unroll
                for (int mi = 0; mi < 2; ++mi) {
                    asm volatile(
                        "mma.sync.aligned.m16n8k8.row.col.f32.tf32.tf32.f32 "
                        "{%0,%1,%2,%3}, {%4,%5,%6,%7}, {%8,%9}, {%0,%1,%2,%3};"
                        : "+f"(acc[mi][nj][0]), "+f"(acc[mi][nj][1]),
                          "+f"(acc[mi][nj][2]), "+f"(acc[mi][nj][3])
                        : "r"(__float_as_uint(a0[mi].x)),
                          "r"(__float_as_uint(a1[mi].x)),
                          "r"(__float_as_uint(a0[mi].y)),
                          "r"(__float_as_uint(a1[mi].y)),
                          "r"(ub0), "r"(ub1));
                }
            }
        }
    }
#undef STAGE_FILL

    // ---- epilogue: relu -> smem [128][128] -> bag-mean(8) -> out ----
    // Cs occupies stages 0..1; last compute used stage 2 -> no clash pre-sync.
    float* Cs = smem;
#pragma unroll
    for (int mi = 0; mi < 2; ++mi) {
#pragma unroll
        for (int nj = 0; nj < 8; ++nj) {
            int r0 = wm * 32 + mi * 16 + g;
            int c0 = wn * 64 + nj * 8 + 2 * t;
            Cs[r0 * BN + c0]           = fmaxf(acc[mi][nj][0], 0.f);
            Cs[r0 * BN + c0 + 1]       = fmaxf(acc[mi][nj][1], 0.f);
            Cs[(r0 + 8) * BN + c0]     = fmaxf(acc[mi][nj][2], 0.f);
            Cs[(r0 + 8) * BN + c0 + 1] = fmaxf(acc[mi][nj][3], 0.f);
        }
    }
    __syncthreads();

    const int col = tid & 127;
    const int h   = tid >> 7;            // 0..1
#pragma unroll
    for (int gg = h; gg < BM / BAG; gg += 2) {
        float s = 0.f;
#pragma unroll
        for (int r = 0; r < BAG; ++r) s += Cs[(gg * BAG + r) * BN + col];
        out[(size_t)(blockIdx.x * (BM / BAG) + gg) * OUTD + blockIdx.y * BN + col]
            = s * (1.f / BAG);
    }
}

// ---------------------------------------------------------------------------
extern "C" void kernel_launch(void* const* d_in, const int* in_sizes, int n_in,
                              void* d_out, int out_size)
{
    (void)in_sizes; (void)n_in; (void)out_size;
    const int*   nodes      = (const int*)  d_in[0];
    const int*   neigh_idx  = (const int*)  d_in[1];
    const float* table_self = (const float*)d_in[2];
    const float* tables_to  = (const float*)d_in[3];
    const float* W_self     = (const float*)d_in[4];
    const float* W_rel      = (const float*)d_in[5];
    const float* W_comp     = (const float*)d_in[6];
    float*       out        = (float*)d_out;

    cudaFuncSetAttribute(gemm_relu_bag_kernel,
                         cudaFuncAttributeMaxDynamicSharedMemorySize,
                         GEMM_SMEM_BYTES);

    // fuse first so the fixed ncu sample slot verifies the fuse fix.
    fuse_weights_kernel<<<512, 256>>>(W_self, W_rel, W_comp);
    gather_mean_kernel<<<dim3(NN / 4, 4), 256>>>(nodes, neigh_idx, table_self, tables_to);
    gemm_relu_bag_kernel<<<dim3(NN / BM, OUTD / BN), 256, GEMM_SMEM_BYTES>>>(out);
}